// round 10
// baseline (speedup 1.0000x reference)
#include <cuda_runtime.h>

// LengthRegulator v5: ONE CTA PER ROW — minimal total work.
//
// Evidence from R6-R9: inner-phase micro-optimizations (binary search vs smem
// scatter vs padded publish vs gmem scatter) all land 8.8-10.9us, because the
// cost is the 16x-redundant per-window row load + block scan across 512 CTAs,
// not the phase work. v5 reads the input once, scans once per row, and
// scatters register-resident runs directly to gmem.
//
//   cs = inclusive cumsum(dur[b]);  token t owns out[b, cs[t-1] .. cs[t])
//   out[b,p] = t+1 there, 0 for p >= cs[N-1]  (d_out is poisoned -> must write)
//
// Grid: 32 CTAs x 1024 threads. 4 tokens/thread (int4 load), warp shfl scan,
// cross-warp scan, then each thread writes its 4 runs (<=15 consecutive floats,
// adjacent lanes -> adjacent segments) and the block strides the zero tail.

#define N_TOK   4096
#define THREADS 1024

__global__ __launch_bounds__(THREADS, 1)
void lr_v5_kernel(const int* __restrict__ dur,
                  float* __restrict__ out,
                  int T) {
    const int b    = blockIdx.x;
    const int tid  = threadIdx.x;
    const int lane = tid & 31;
    const int wid  = tid >> 5;

    __shared__ int s_wsum[32];
    __shared__ int s_woff[33];          // [32] = row total

    // ---- 1) 4 tokens per thread, local inclusive scan ----
    int4 d = ((const int4*)(dur + b * N_TOK))[tid];
    const int c0 = d.x;
    const int c1 = c0 + d.y;
    const int c2 = c1 + d.z;
    const int c3 = c2 + d.w;
    const int my_total = c3;

    // ---- 2) warp inclusive scan of per-thread totals ----
    int s = my_total;
    #pragma unroll
    for (int o = 1; o < 32; o <<= 1) {
        int u = __shfl_up_sync(0xffffffffu, s, o);
        if (lane >= o) s += u;
    }
    if (lane == 31) s_wsum[wid] = s;
    __syncthreads();

    // ---- 3) scan of the 32 warp totals (warp 0) ----
    if (wid == 0) {
        int vv = s_wsum[lane];
        #pragma unroll
        for (int o = 1; o < 32; o <<= 1) {
            int u = __shfl_up_sync(0xffffffffu, vv, o);
            if (lane >= o) vv += u;
        }
        s_woff[lane + 1] = vv;
        if (lane == 0) s_woff[0] = 0;
    }
    __syncthreads();

    const int base  = s_woff[wid] + (s - my_total);   // exclusive prefix for thread
    const int total = s_woff[32];

    // ---- 4) scatter this thread's 4 runs straight to gmem ----
    float* orow = out + b * T;
    {
        const int tok0 = tid << 2;
        const int st0 = base,      en0 = base + c0;
        const int st1 = base + c0, en1 = base + c1;
        const int st2 = base + c1, en2 = base + c2;
        const int st3 = base + c2, en3 = base + c3;

        for (int p = st0; p < en0; p++) orow[p] = (float)(tok0 + 1);
        for (int p = st1; p < en1; p++) orow[p] = (float)(tok0 + 2);
        for (int p = st2; p < en2; p++) orow[p] = (float)(tok0 + 3);
        for (int p = st3; p < en3; p++) orow[p] = (float)(tok0 + 4);
    }

    // ---- 5) zero-fill the padded tail [total, T) ----
    for (int p = total + tid; p < T; p += THREADS)
        orow[p] = 0.0f;
}

extern "C" void kernel_launch(void* const* d_in, const int* in_sizes, int n_in,
                              void* d_out, int out_size) {
    const int* dur = (const int*)d_in[0];
    float*     out = (float*)d_out;
    const int  B = 32;
    const int  T = out_size / B;

    lr_v5_kernel<<<B, THREADS>>>(dur, out, T);
}

// round 11
// speedup vs baseline: 1.9299x; 1.9299x over previous
#include <cuda_runtime.h>

// LengthRegulator v6: two-kernel split.
//  K1 (32 CTAs): row cumsum -> gmem scratch (coalesced int4) + per-window
//     start-token index (detected from register-resident runs, unique writer).
//  K2 (~512 CTAs): per 2048-wide window, stride tokens from start index,
//     coalesced LDG of cs[t-1],cs[t] from L2, scatter runs to gmem, tail fill.
//
// Rationale (R6-R10 evidence): scatter wavefront cost needs MANY SMs (v5 on 32
// SMs = 22.8us), but per-window redundant load+scan caps 512-CTA variants at
// ~9us. Split gives many SMs AND near-zero per-CTA setup in the fill kernel.

#define N_TOK       4096
#define B_ROWS      32
#define OUT_PER_CTA 2048
#define MAX_WIN     64
#define K2_THREADS  256

__device__ int g_cs[B_ROWS * N_TOK];          // inclusive cumsum per row
__device__ int g_start[B_ROWS * MAX_WIN];     // first token intersecting window

// ---------------- K1: cumsum + window starts ----------------
__global__ __launch_bounds__(1024, 1)
void lr_v6_cumsum(const int* __restrict__ dur, int nblk) {
    const int b    = blockIdx.x;
    const int tid  = threadIdx.x;
    const int lane = tid & 31;
    const int wid  = tid >> 5;

    __shared__ int s_wsum[32];
    __shared__ int s_woff[33];

    // init window starts to "no token" (N_TOK) — tail windows skip the scatter
    if (tid < MAX_WIN) g_start[b * MAX_WIN + tid] = N_TOK;

    // 4 tokens per thread
    int4 d = ((const int4*)(dur + b * N_TOK))[tid];
    const int c0 = d.x;
    const int c1 = c0 + d.y;
    const int c2 = c1 + d.z;
    const int c3 = c2 + d.w;
    const int my_total = c3;

    // warp scan of thread totals
    int s = my_total;
    #pragma unroll
    for (int o = 1; o < 32; o <<= 1) {
        int u = __shfl_up_sync(0xffffffffu, s, o);
        if (lane >= o) s += u;
    }
    if (lane == 31) s_wsum[wid] = s;
    __syncthreads();

    if (wid == 0) {
        int vv = s_wsum[lane];
        #pragma unroll
        for (int o = 1; o < 32; o <<= 1) {
            int u = __shfl_up_sync(0xffffffffu, vv, o);
            if (lane >= o) vv += u;
        }
        s_woff[lane + 1] = vv;
        if (lane == 0) s_woff[0] = 0;
    }
    __syncthreads();

    const int base = s_woff[wid] + (s - my_total);

    // write inclusive cumsum, coalesced int4
    int4 cs4;
    cs4.x = base + c0; cs4.y = base + c1; cs4.z = base + c2; cs4.w = base + c3;
    ((int4*)(g_cs + b * N_TOK))[tid] = cs4;

    // window-start detection: token t (run [st,en), en-st<16) contains boundary
    // w*2048 iff st <= w*2048 < en; at most one w per token; unique writer.
    const int tok0 = tid << 2;
    int stv[4] = { base,      base + c0, base + c1, base + c2 };
    int env[4] = { base + c0, base + c1, base + c2, base + c3 };
    #pragma unroll
    for (int i = 0; i < 4; i++) {
        const int st = stv[i], en = env[i];
        if (en > st) {
            const int w = (st + OUT_PER_CTA - 1) / OUT_PER_CTA;   // ceil
            if (w < nblk && w * OUT_PER_CTA < en)
                g_start[b * MAX_WIN + w] = tok0 + i;
        }
    }
}

// ---------------- K2: window fill ----------------
__global__ __launch_bounds__(K2_THREADS)
void lr_v6_fill(float* __restrict__ out, int T, int nblk) {
    const int b     = blockIdx.x / nblk;
    const int chunk = blockIdx.x % nblk;
    const int tid   = threadIdx.x;

    const int* cs = g_cs + b * N_TOK;
    const int p0    = chunk * OUT_PER_CTA;
    const int p_end = (p0 + OUT_PER_CTA < T) ? p0 + OUT_PER_CTA : T;

    const int total = cs[N_TOK - 1];            // broadcast, L2/L1-cached
    int p1 = (p_end < total) ? p_end : total;

    float* orow = out + b * T;

    // scatter: tokens strided across threads from the window's start token.
    // cs[t-1], cs[t] loads are coalesced across lanes (adjacent addresses).
    const int t0 = g_start[b * MAX_WIN + chunk];
    for (int t = t0 + tid; t < N_TOK; t += K2_THREADS) {
        const int st = (t == 0) ? 0 : cs[t - 1];
        if (st >= p1) break;                     // cs monotone: safe per-thread
        int en = cs[t];
        if (en > p1) en = p1;
        const float val = (float)(t + 1);
        for (int p = (st > p0 ? st : p0); p < en; p++)
            orow[p] = val;
    }

    // zero tail of this window: [max(p0,total), p_end)
    const int z0 = (p0 > total) ? p0 : total;
    for (int p = z0 + tid; p < p_end; p += K2_THREADS)
        orow[p] = 0.0f;
}

extern "C" void kernel_launch(void* const* d_in, const int* in_sizes, int n_in,
                              void* d_out, int out_size) {
    const int* dur = (const int*)d_in[0];
    float*     out = (float*)d_out;
    const int  T    = out_size / B_ROWS;
    int nblk = (T + OUT_PER_CTA - 1) / OUT_PER_CTA;
    if (nblk > MAX_WIN) nblk = MAX_WIN;          // T <= 4096*15 -> nblk <= 30

    lr_v6_cumsum<<<B_ROWS, 1024>>>(dur, nblk);
    lr_v6_fill<<<B_ROWS * nblk, K2_THREADS>>>(out, T, nblk);
}

// round 12
// speedup vs baseline: 2.6920x; 1.3949x over previous
#include <cuda_runtime.h>

// LengthRegulator v7 = v2 (best measured: 8.77us kernel) with its two known
// inefficiencies removed:
//   1) cumsum publish padded to stride 17 -> conflict-free (v2: 16-way conflicts)
//   2) window start token via register-resident boundary detection (one STS)
//      instead of a 12-step broadcast binary search chain.
// Back half unchanged from v2: parallel strided-token scatter into a zeroed
// shared tile + coalesced scalar stores to gmem (the only global-store pattern
// that measured fastest across R6-R11).
//
//   cs = inclusive cumsum(dur[b]);  token t owns out[b, cs[t-1] .. cs[t])
//   out[b,p] = t+1 there, 0 for p >= cs[N-1]   (d_out poisoned -> always write)

#define N_TOK       4096
#define THREADS     256
#define PER_THREAD  (N_TOK / THREADS)                  // 16 tokens per thread
#define OUT_PER_CTA 2048
#define PAD(t)      ((((t) >> 4) * 17) + ((t) & 15))   // stride-17 padded index

__global__ __launch_bounds__(THREADS)
void lr_v7_kernel(const int* __restrict__ dur,
                  float* __restrict__ out,
                  int T, int nblk) {
    const int b     = blockIdx.x / nblk;
    const int chunk = blockIdx.x % nblk;
    const int tid   = threadIdx.x;
    const int lane  = tid & 31;
    const int wid   = tid >> 5;

    __shared__ int   s_cs[THREADS * 17];       // padded cumsum
    __shared__ float s_out[OUT_PER_CTA];       // staging tile
    __shared__ int   s_wsum[THREADS / 32];
    __shared__ int   s_woff[THREADS / 32 + 1]; // [8] = row total
    __shared__ int   s_t0;                     // first token intersecting window

    // ---- 1) load 16 contiguous durations per thread, local inclusive scan ----
    int v[PER_THREAD];
    {
        const int4* d4 = (const int4*)(dur + b * N_TOK) + tid * 4;
        int4 a = d4[0], c = d4[1], e = d4[2], f = d4[3];
        v[0]  = a.x; v[1]  = a.y; v[2]  = a.z; v[3]  = a.w;
        v[4]  = c.x; v[5]  = c.y; v[6]  = c.z; v[7]  = c.w;
        v[8]  = e.x; v[9]  = e.y; v[10] = e.z; v[11] = e.w;
        v[12] = f.x; v[13] = f.y; v[14] = f.z; v[15] = f.w;
    }
    #pragma unroll
    for (int i = 1; i < PER_THREAD; i++) v[i] += v[i - 1];
    const int my_total = v[PER_THREAD - 1];

    // ---- 2) warp inclusive scan of per-thread totals ----
    int s = my_total;
    #pragma unroll
    for (int o = 1; o < 32; o <<= 1) {
        int u = __shfl_up_sync(0xffffffffu, s, o);
        if (lane >= o) s += u;
    }
    if (lane == 31) s_wsum[wid] = s;
    if (tid == 0)   s_t0 = N_TOK;              // default: no token in window

    // zero the output tile while the scan settles (8 floats / thread)
    #pragma unroll
    for (int k = 0; k < OUT_PER_CTA / THREADS; k++)
        s_out[k * THREADS + tid] = 0.0f;
    __syncthreads();

    // ---- 3) serial scan of the 8 warp totals ----
    if (tid == 0) {
        int acc = 0;
        #pragma unroll
        for (int w = 0; w < THREADS / 32; w++) { s_woff[w] = acc; acc += s_wsum[w]; }
        s_woff[THREADS / 32] = acc;
    }
    __syncthreads();

    const int base  = s_woff[wid] + (s - my_total);   // exclusive thread prefix
    const int total = s_woff[THREADS / 32];

    const int p0    = chunk * OUT_PER_CTA;
    const int p_end = (p0 + OUT_PER_CTA < T) ? p0 + OUT_PER_CTA : T;
    int p1 = (p_end < total) ? p_end : total;

    // ---- 4) publish padded cumsum + detect window-start token in registers ----
    // token (tid*16+i) has run [base+v[i-1], base+v[i]); the unique thread whose
    // run contains p0 records it. p0==0 start handled by t0 default via search
    // over runs: run containing p0 means st <= p0 < en.
    {
        int prev = 0;
        #pragma unroll
        for (int i = 0; i < PER_THREAD; i++) {
            s_cs[tid * 17 + i] = base + v[i];
            const int st = base + prev, en = base + v[i];
            if (st <= p0 && p0 < en) s_t0 = tid * PER_THREAD + i;
            prev = v[i];
        }
    }
    __syncthreads();

    // ---- 5) scatter: tokens strided across threads into the shared tile ----
    if (p0 < p1) {
        const int t0 = s_t0;
        for (int t = t0 + tid; t < N_TOK; t += THREADS) {
            const int st = (t == 0) ? 0 : s_cs[PAD(t - 1)];
            if (st >= p1) break;                 // cs monotone: safe per-thread
            int en = s_cs[PAD(t)];
            if (en > p1) en = p1;
            const float val = (float)(t + 1);
            for (int p = (st > p0 ? st : p0); p < en; p++)
                s_out[p - p0] = val;
        }
    }
    __syncthreads();

    // ---- 6) stream tile to global, coalesced scalar (alignment-proof) ----
    float* orow = out + b * T;
    #pragma unroll
    for (int k = 0; k < OUT_PER_CTA / THREADS; k++) {
        const int idx = k * THREADS + tid;
        const int p   = p0 + idx;
        if (p < T) orow[p] = s_out[idx];
    }
}

extern "C" void kernel_launch(void* const* d_in, const int* in_sizes, int n_in,
                              void* d_out, int out_size) {
    const int* dur = (const int*)d_in[0];
    float*     out = (float*)d_out;
    const int  B    = 32;
    const int  T    = out_size / B;
    const int  nblk = (T + OUT_PER_CTA - 1) / OUT_PER_CTA;

    lr_v7_kernel<<<B * nblk, THREADS>>>(dur, out, T, nblk);
}